// round 1
// baseline (speedup 1.0000x reference)
#include <cuda_runtime.h>
#include <math.h>

#define Bn 512
#define Ln 50
#define Nn 64
#define En 16
#define Hn 128
#define Dn 256
#define ITEMN 100000
#define EPS 1e-12f

// ------------------------- scratch (no allocs allowed) -------------------------
__device__ float g_nodes_h[Bn * Nn * Hn];          // 16.8 MB
__device__ float g_seqnorm[Bn * Dn];               // 0.5 MB
__device__ float g_itemnorm[(size_t)ITEMN * Dn];   // 102.4 MB

// =============================================================================
// Kernel 1: per-batch hypergraph GNN. One CTA per batch, everything in smem.
//   n_h init = l2norm(embedding[nodes]); 2 steps of edge/node propagation.
// =============================================================================
__global__ void __launch_bounds__(256, 1)
hgnn_kernel(const int* __restrict__ nodes, const float* __restrict__ hn_adj,
            const float* __restrict__ embedding,
            const float* __restrict__ w_edge, const float* __restrict__ w_node) {
    extern __shared__ float sm[];
    float* s_we   = sm;                 // 16384
    float* s_wn   = s_we + 16384;       // 16384
    float* s_nh   = s_wn + 16384;       // 8192
    float* s_tmp  = s_nh + 8192;        // 8192
    float* s_eh   = s_tmp + 8192;       // 2048
    float* s_adj  = s_eh + 2048;        // 1024
    float* s_dege = s_adj + 1024;       // 16
    float* s_degn = s_dege + 16;        // 64
    int*   s_idx  = (int*)(s_degn + 64);// 64

    const int b = blockIdx.x;
    const int t = threadIdx.x;
    const int lane = t & 31, wid = t >> 5;

    // load weights into smem (reused 2x each by all rows)
    {
        const float4* we4 = (const float4*)w_edge;
        const float4* wn4 = (const float4*)w_node;
        float4* swe4 = (float4*)s_we;
        float4* swn4 = (float4*)s_wn;
        for (int i = t; i < 4096; i += 256) { swe4[i] = we4[i]; swn4[i] = wn4[i]; }
    }
    // adj + node ids
    {
        const float* adjb = hn_adj + (size_t)b * Nn * En;
        for (int i = t; i < Nn * En; i += 256) s_adj[i] = adjb[i];
        if (t < Nn) s_idx[t] = nodes[b * Nn + t];
    }
    __syncthreads();

    // degrees
    if (t < En) {
        float s = 0.f;
        #pragma unroll 8
        for (int n = 0; n < Nn; n++) s += s_adj[n * En + t];
        s_dege[t] = fmaxf(s, 1.0f);
    }
    if (t >= 32 && t < 32 + Nn) {
        int n = t - 32;
        float s = 0.f;
        #pragma unroll
        for (int e = 0; e < En; e++) s += s_adj[n * En + e];
        s_degn[n] = fmaxf(s, 1.0f);
    }

    // init n_h = l2norm(embedding[nodes]) — warp per row
    for (int n = wid; n < Nn; n += 8) {
        const float4 v = ((const float4*)(embedding + (size_t)s_idx[n] * Hn))[lane];
        float ss = v.x * v.x + v.y * v.y + v.z * v.z + v.w * v.w;
        #pragma unroll
        for (int o = 16; o > 0; o >>= 1) ss += __shfl_xor_sync(0xffffffffu, ss, o);
        const float inv = 1.0f / fmaxf(sqrtf(ss), EPS);
        ((float4*)(s_nh + n * Hn))[lane] = make_float4(v.x * inv, v.y * inv, v.z * inv, v.w * inv);
    }
    __syncthreads();

    for (int step = 0; step < 2; step++) {
        // agg_e[e,d] = (sum_n adj[n,e] * n_h[n,d]) / deg_e[e]   -> s_tmp[0..16)
        {
            const int d = t & 127;
            for (int e = t >> 7; e < En; e += 2) {
                float acc = 0.f;
                #pragma unroll 8
                for (int n = 0; n < Nn; n++) acc += s_adj[n * En + e] * s_nh[n * Hn + d];
                s_tmp[e * Hn + d] = acc / s_dege[e];
            }
        }
        __syncthreads();
        // e_h = agg_e @ w_edge  (16x128 @ 128x128), 2 rows x 4 cols per thread
        {
            const int c = t & 31, r = t >> 5;   // c: j-tile (4 cols), r: 2 rows
            float a00=0,a01=0,a02=0,a03=0, a10=0,a11=0,a12=0,a13=0;
            for (int d = 0; d < Hn; d++) {
                const float4 w = *(const float4*)(s_we + d * Hn + c * 4);
                const float t0 = s_tmp[(r * 2 + 0) * Hn + d];
                const float t1 = s_tmp[(r * 2 + 1) * Hn + d];
                a00 += t0 * w.x; a01 += t0 * w.y; a02 += t0 * w.z; a03 += t0 * w.w;
                a10 += t1 * w.x; a11 += t1 * w.y; a12 += t1 * w.z; a13 += t1 * w.w;
            }
            *(float4*)(s_eh + (r * 2 + 0) * Hn + c * 4) = make_float4(a00, a01, a02, a03);
            *(float4*)(s_eh + (r * 2 + 1) * Hn + c * 4) = make_float4(a10, a11, a12, a13);
        }
        __syncthreads();
        // agg_n[n,d] = (sum_e adj[n,e] * e_h[e,d]) / deg_n[n]  -> s_tmp[0..64)
        {
            const int d = t & 127;
            for (int n = t >> 7; n < Nn; n += 2) {
                float acc = 0.f;
                #pragma unroll
                for (int e = 0; e < En; e++) acc += s_adj[n * En + e] * s_eh[e * Hn + d];
                s_tmp[n * Hn + d] = acc / s_degn[n];
            }
        }
        __syncthreads();
        // n_h = agg_n @ w_node  (64x128 @ 128x128), 8 rows x 4 cols per thread
        {
            const int c = t & 31, r = t >> 5;   // rows r*8 .. r*8+7
            float acc[8][4];
            #pragma unroll
            for (int rr = 0; rr < 8; rr++) { acc[rr][0]=0; acc[rr][1]=0; acc[rr][2]=0; acc[rr][3]=0; }
            for (int d = 0; d < Hn; d++) {
                const float4 w = *(const float4*)(s_wn + d * Hn + c * 4);
                #pragma unroll
                for (int rr = 0; rr < 8; rr++) {
                    const float tv = s_tmp[(r * 8 + rr) * Hn + d];
                    acc[rr][0] += tv * w.x; acc[rr][1] += tv * w.y;
                    acc[rr][2] += tv * w.z; acc[rr][3] += tv * w.w;
                }
            }
            #pragma unroll
            for (int rr = 0; rr < 8; rr++)
                *(float4*)(s_nh + (r * 8 + rr) * Hn + c * 4) =
                    make_float4(acc[rr][0], acc[rr][1], acc[rr][2], acc[rr][3]);
        }
        __syncthreads();
    }

    // write final node hidden
    {
        float4* out4 = (float4*)(g_nodes_h + (size_t)b * Nn * Hn);
        const float4* in4 = (const float4*)s_nh;
        for (int i = t; i < Nn * Hn / 4; i += 256) out4[i] = in4[i];
    }
}

// =============================================================================
// Kernel 2: sequence assembly + SR-GNN attention readout. One CTA per batch.
// Produces l2norm(seq_output) into g_seqnorm.
// =============================================================================
__global__ void __launch_bounds__(256, 1)
attn_kernel(const int* __restrict__ item_seq, const int* __restrict__ alias_item,
            const int* __restrict__ alias_cate,
            const float* __restrict__ q1_w, const float* __restrict__ q1_b,
            const float* __restrict__ q2_w, const float* __restrict__ v_w) {
    extern __shared__ float s_seq[];        // [50][256] = 51.2 KB
    __shared__ float s_q1[Dn];
    __shared__ float s_mask[64];
    __shared__ float s_red[8];
    __shared__ float s_bcast;
    __shared__ int   s_last;

    const int b = blockIdx.x;
    const int t = threadIdx.x;
    const int lane = t & 31, wid = t >> 5;

    if (t < Ln) s_mask[t] = (item_seq[b * Ln + t] > 0) ? 1.0f : 0.0f;
    if (t == 0) {
        int cnt = 0;
        for (int l = 0; l < Ln; l++) cnt += (item_seq[b * Ln + l] > 0) ? 1 : 0;
        s_last = max(cnt - 1, 0);
    }

    // seq_hidden = l2norm(concat(nodes_h[alias_item], nodes_h[alias_cate])) — warp per l
    for (int l = wid; l < Ln; l += 8) {
        const int ai = alias_item[b * Ln + l];
        const int ac = alias_cate[b * Ln + l];
        const float4 vi = ((const float4*)(g_nodes_h + ((size_t)b * Nn + ai) * Hn))[lane];
        const float4 vc = ((const float4*)(g_nodes_h + ((size_t)b * Nn + ac) * Hn))[lane];
        float ss = vi.x*vi.x + vi.y*vi.y + vi.z*vi.z + vi.w*vi.w
                 + vc.x*vc.x + vc.y*vc.y + vc.z*vc.z + vc.w*vc.w;
        #pragma unroll
        for (int o = 16; o > 0; o >>= 1) ss += __shfl_xor_sync(0xffffffffu, ss, o);
        const float inv = 1.0f / fmaxf(sqrtf(ss), EPS);
        ((float4*)(s_seq + l * Dn))[lane]      = make_float4(vi.x*inv, vi.y*inv, vi.z*inv, vi.w*inv);
        ((float4*)(s_seq + l * Dn))[lane + 32] = make_float4(vc.x*inv, vc.y*inv, vc.z*inv, vc.w*inv);
    }
    __syncthreads();

    // q1[j] = ht @ q1_w + q1_b   (thread j = t)
    {
        const int last = s_last;
        float acc = 0.f;
        for (int d = 0; d < Dn; d++) acc += s_seq[last * Dn + d] * q1_w[d * Dn + t];
        s_q1[t] = acc + q1_b[t];
    }

    // q2[l][j] accumulated in registers (thread owns column j = t)
    float q2acc[Ln];
    #pragma unroll
    for (int l = 0; l < Ln; l++) q2acc[l] = 0.f;
    for (int d = 0; d < Dn; d++) {
        const float w = q2_w[d * Dn + t];
        #pragma unroll
        for (int l = 0; l < Ln; l++) q2acc[l] += s_seq[l * Dn + d] * w;
    }

    // alpha + weighted sum
    const float vw = v_w[t];
    const float q1v = s_q1[t];
    float outacc = 0.f;
    for (int l = 0; l < Ln; l++) {
        const float x = q1v + q2acc[l];
        const float val = 1.0f / (1.0f + expf(-x));
        float c = val * vw;
        #pragma unroll
        for (int o = 16; o > 0; o >>= 1) c += __shfl_xor_sync(0xffffffffu, c, o);
        if (lane == 0) s_red[wid] = c;
        __syncthreads();
        if (t == 0) {
            float a = 0.f;
            #pragma unroll
            for (int w = 0; w < 8; w++) a += s_red[w];
            s_bcast = a;
        }
        __syncthreads();
        outacc += s_bcast * s_mask[l] * s_seq[l * Dn + t];
    }

    // l2norm(seq_output) -> g_seqnorm
    {
        float ss = outacc * outacc;
        #pragma unroll
        for (int o = 16; o > 0; o >>= 1) ss += __shfl_xor_sync(0xffffffffu, ss, o);
        if (lane == 0) s_red[wid] = ss;
        __syncthreads();
        if (t == 0) {
            float a = 0.f;
            #pragma unroll
            for (int w = 0; w < 8; w++) a += s_red[w];
            s_bcast = a;
        }
        __syncthreads();
        const float inv = 1.0f / fmaxf(sqrtf(s_bcast), EPS);
        g_seqnorm[b * Dn + t] = outacc * inv;
    }
}

// =============================================================================
// Kernel 3: item_norm[i] = l2norm(concat(embedding[i], embedding[item_cates[i]]))
// Warp per row (8 rows per CTA).
// =============================================================================
__global__ void __launch_bounds__(256)
itemnorm_kernel(const float* __restrict__ embedding, const int* __restrict__ item_cates) {
    const int i = blockIdx.x * 8 + (threadIdx.x >> 5);
    const int lane = threadIdx.x & 31;
    if (i >= ITEMN) return;
    const int c = item_cates[i];
    const float4 vi = ((const float4*)(embedding + (size_t)i * Hn))[lane];
    const float4 vc = ((const float4*)(embedding + (size_t)c * Hn))[lane];
    float ss = vi.x*vi.x + vi.y*vi.y + vi.z*vi.z + vi.w*vi.w
             + vc.x*vc.x + vc.y*vc.y + vc.z*vc.z + vc.w*vc.w;
    #pragma unroll
    for (int o = 16; o > 0; o >>= 1) ss += __shfl_xor_sync(0xffffffffu, ss, o);
    const float inv = 1.0f / fmaxf(sqrtf(ss), EPS);
    float4* dst = (float4*)(g_itemnorm + (size_t)i * Dn);
    dst[lane]      = make_float4(vi.x*inv, vi.y*inv, vi.z*inv, vi.w*inv);
    dst[lane + 32] = make_float4(vc.x*inv, vc.y*inv, vc.z*inv, vc.w*inv);
}

// =============================================================================
// Kernel 4: scores = 16 * seqnorm[512,256] @ itemnorm[100000,256]^T
// Tiled SGEMM: CTA = 128 items x 128 batch rows, thread = 8x8, K chunks of 16.
// =============================================================================
__global__ void __launch_bounds__(256, 2)
scores_kernel(float* __restrict__ C) {
    __shared__ float sA[16][132];   // [k][item]
    __shared__ float sB[16][132];   // [k][batch]
    const int i0 = blockIdx.x * 128;
    const int b0 = blockIdx.y * 128;
    const int t = threadIdx.x;
    const int tx = t & 15, ty = t >> 4;
    const int lr = t >> 2;          // 0..63
    const int lk = (t & 3) << 2;    // 0,4,8,12

    float acc[8][8];
    #pragma unroll
    for (int ib = 0; ib < 8; ib++)
        #pragma unroll
        for (int ia = 0; ia < 8; ia++) acc[ib][ia] = 0.f;

    for (int k0 = 0; k0 < 256; k0 += 16) {
        if (k0) __syncthreads();
        #pragma unroll
        for (int h = 0; h < 2; h++) {
            const int irow = i0 + lr + h * 64;
            float4 v = make_float4(0.f, 0.f, 0.f, 0.f);
            if (irow < ITEMN) v = *(const float4*)(g_itemnorm + (size_t)irow * Dn + k0 + lk);
            sA[lk + 0][lr + h * 64] = v.x;
            sA[lk + 1][lr + h * 64] = v.y;
            sA[lk + 2][lr + h * 64] = v.z;
            sA[lk + 3][lr + h * 64] = v.w;
            const int brow = b0 + lr + h * 64;
            const float4 u = *(const float4*)(g_seqnorm + (size_t)brow * Dn + k0 + lk);
            sB[lk + 0][lr + h * 64] = u.x;
            sB[lk + 1][lr + h * 64] = u.y;
            sB[lk + 2][lr + h * 64] = u.z;
            sB[lk + 3][lr + h * 64] = u.w;
        }
        __syncthreads();
        #pragma unroll
        for (int k = 0; k < 16; k++) {
            const float4 a0 = *(const float4*)&sA[k][tx * 4];
            const float4 a1 = *(const float4*)&sA[k][tx * 4 + 64];
            const float4 bb0 = *(const float4*)&sB[k][ty * 4];
            const float4 bb1 = *(const float4*)&sB[k][ty * 4 + 64];
            const float av[8] = {a0.x, a0.y, a0.z, a0.w, a1.x, a1.y, a1.z, a1.w};
            const float bv[8] = {bb0.x, bb0.y, bb0.z, bb0.w, bb1.x, bb1.y, bb1.z, bb1.w};
            #pragma unroll
            for (int ib = 0; ib < 8; ib++)
                #pragma unroll
                for (int ia = 0; ia < 8; ia++)
                    acc[ib][ia] += bv[ib] * av[ia];
        }
    }

    #pragma unroll
    for (int ib = 0; ib < 8; ib++) {
        const int brow = b0 + ty * 4 + ((ib < 4) ? ib : 60 + ib);
        float* crow = C + (size_t)brow * ITEMN;
        const int ic0 = i0 + tx * 4;
        if (ic0 < ITEMN)
            *(float4*)(crow + ic0) = make_float4(16.f * acc[ib][0], 16.f * acc[ib][1],
                                                 16.f * acc[ib][2], 16.f * acc[ib][3]);
        const int ic1 = i0 + 64 + tx * 4;
        if (ic1 < ITEMN)
            *(float4*)(crow + ic1) = make_float4(16.f * acc[ib][4], 16.f * acc[ib][5],
                                                 16.f * acc[ib][6], 16.f * acc[ib][7]);
    }
}

// =============================================================================
// launch
// =============================================================================
extern "C" void kernel_launch(void* const* d_in, const int* in_sizes, int n_in,
                              void* d_out, int out_size) {
    const int*   item_seq   = (const int*)  d_in[0];
    /* label d_in[1] unused */
    const int*   nodes      = (const int*)  d_in[2];
    const float* hn_adj     = (const float*)d_in[3];
    const int*   alias_item = (const int*)  d_in[4];
    const int*   alias_cate = (const int*)  d_in[5];
    const float* embedding  = (const float*)d_in[6];
    const int*   item_cates = (const int*)  d_in[7];
    const float* w_edge     = (const float*)d_in[8];
    const float* w_node     = (const float*)d_in[9];
    const float* q1_w       = (const float*)d_in[10];
    const float* q1_b       = (const float*)d_in[11];
    const float* q2_w       = (const float*)d_in[12];
    const float* v_w        = (const float*)d_in[13];
    float* out = (float*)d_out;

    const int hg_smem  = (16384 + 16384 + 8192 + 8192 + 2048 + 1024 + 16 + 64 + 64) * 4; // ~209.5 KB
    const int seq_smem = Ln * Dn * 4;                                                    // 51.2 KB
    cudaFuncSetAttribute(hgnn_kernel, cudaFuncAttributeMaxDynamicSharedMemorySize, hg_smem);
    cudaFuncSetAttribute(attn_kernel, cudaFuncAttributeMaxDynamicSharedMemorySize, seq_smem);

    hgnn_kernel<<<Bn, 256, hg_smem>>>(nodes, hn_adj, embedding, w_edge, w_node);
    attn_kernel<<<Bn, 256, seq_smem>>>(item_seq, alias_item, alias_cate, q1_w, q1_b, q2_w, v_w);
    itemnorm_kernel<<<(ITEMN + 7) / 8, 256>>>(embedding, item_cates);
    scores_kernel<<<dim3((ITEMN + 127) / 128, Bn / 128), 256>>>(out);
}

// round 3
// speedup vs baseline: 1.3319x; 1.3319x over previous
#include <cuda_runtime.h>
#include <cuda_bf16.h>
#include <math.h>
#include <stdint.h>

#define Bn 512
#define Ln 50
#define Nn 64
#define En 16
#define Hn 128
#define Dn 256
#define ITEMN 100000
#define ITEMP 100096   // padded to multiple of 128
#define EPS 1e-12f

// ------------------------- scratch (no allocs allowed) -------------------------
__device__ float g_nodes_h[Bn * Nn * Hn];                    // 16.8 MB
__device__ __nv_bfloat16 g_item_hi[(size_t)ITEMP * Dn];      // 51.2 MB
__device__ __nv_bfloat16 g_item_lo[(size_t)ITEMP * Dn];      // 51.2 MB
__device__ __nv_bfloat16 g_seq_hi[Bn * Dn];
__device__ __nv_bfloat16 g_seq_lo[Bn * Dn];

// ============================= PTX helpers =============================
__device__ __forceinline__ uint32_t smem_u32(const void* p) {
    uint32_t a;
    asm("{ .reg .u64 t; cvta.to.shared.u64 t, %1; cvt.u32.u64 %0, t; }" : "=r"(a) : "l"(p));
    return a;
}
__device__ __forceinline__ void cp16(uint32_t dst, const void* src) {
    asm volatile("cp.async.cg.shared.global [%0], [%1], 16;" :: "r"(dst), "l"(src));
}
#define CP_COMMIT() asm volatile("cp.async.commit_group;" ::: "memory")
#define CP_WAIT(n)  asm volatile("cp.async.wait_group %0;" :: "n"(n) : "memory")

__device__ __forceinline__ void ldsm4(uint32_t* r, uint32_t addr) {
    asm volatile("ldmatrix.sync.aligned.m8n8.x4.shared.b16 {%0,%1,%2,%3}, [%4];"
                 : "=r"(r[0]), "=r"(r[1]), "=r"(r[2]), "=r"(r[3]) : "r"(addr));
}
__device__ __forceinline__ void mma16816(float* d, const uint32_t* a, const uint32_t* b) {
    asm volatile(
        "mma.sync.aligned.m16n8k16.row.col.f32.bf16.bf16.f32 "
        "{%0,%1,%2,%3}, {%4,%5,%6,%7}, {%8,%9}, {%0,%1,%2,%3};"
        : "+f"(d[0]), "+f"(d[1]), "+f"(d[2]), "+f"(d[3])
        : "r"(a[0]), "r"(a[1]), "r"(a[2]), "r"(a[3]), "r"(b[0]), "r"(b[1]));
}

// =============================================================================
// Kernel 1: per-batch hypergraph GNN. One CTA per batch, everything in smem.
// =============================================================================
__global__ void __launch_bounds__(256, 1)
hgnn_kernel(const int* __restrict__ nodes, const float* __restrict__ hn_adj,
            const float* __restrict__ embedding,
            const float* __restrict__ w_edge, const float* __restrict__ w_node) {
    extern __shared__ float sm[];
    float* s_we   = sm;                 // 16384
    float* s_wn   = s_we + 16384;       // 16384
    float* s_nh   = s_wn + 16384;       // 8192
    float* s_tmp  = s_nh + 8192;        // 8192
    float* s_eh   = s_tmp + 8192;       // 2048
    float* s_adj  = s_eh + 2048;        // 1024
    float* s_dege = s_adj + 1024;       // 16
    float* s_degn = s_dege + 16;        // 64
    int*   s_idx  = (int*)(s_degn + 64);// 64

    const int b = blockIdx.x;
    const int t = threadIdx.x;
    const int lane = t & 31, wid = t >> 5;

    {
        const float4* we4 = (const float4*)w_edge;
        const float4* wn4 = (const float4*)w_node;
        float4* swe4 = (float4*)s_we;
        float4* swn4 = (float4*)s_wn;
        for (int i = t; i < 4096; i += 256) { swe4[i] = we4[i]; swn4[i] = wn4[i]; }
    }
    {
        const float* adjb = hn_adj + (size_t)b * Nn * En;
        for (int i = t; i < Nn * En; i += 256) s_adj[i] = adjb[i];
        if (t < Nn) s_idx[t] = nodes[b * Nn + t];
    }
    __syncthreads();

    if (t < En) {
        float s = 0.f;
        #pragma unroll 8
        for (int n = 0; n < Nn; n++) s += s_adj[n * En + t];
        s_dege[t] = fmaxf(s, 1.0f);
    }
    if (t >= 32 && t < 32 + Nn) {
        int n = t - 32;
        float s = 0.f;
        #pragma unroll
        for (int e = 0; e < En; e++) s += s_adj[n * En + e];
        s_degn[n] = fmaxf(s, 1.0f);
    }

    for (int n = wid; n < Nn; n += 8) {
        const float4 v = ((const float4*)(embedding + (size_t)s_idx[n] * Hn))[lane];
        float ss = v.x * v.x + v.y * v.y + v.z * v.z + v.w * v.w;
        #pragma unroll
        for (int o = 16; o > 0; o >>= 1) ss += __shfl_xor_sync(0xffffffffu, ss, o);
        const float inv = 1.0f / fmaxf(sqrtf(ss), EPS);
        ((float4*)(s_nh + n * Hn))[lane] = make_float4(v.x * inv, v.y * inv, v.z * inv, v.w * inv);
    }
    __syncthreads();

    for (int step = 0; step < 2; step++) {
        {
            const int d = t & 127;
            for (int e = t >> 7; e < En; e += 2) {
                float acc = 0.f;
                #pragma unroll 8
                for (int n = 0; n < Nn; n++) acc += s_adj[n * En + e] * s_nh[n * Hn + d];
                s_tmp[e * Hn + d] = acc / s_dege[e];
            }
        }
        __syncthreads();
        {
            const int c = t & 31, r = t >> 5;
            float a00=0,a01=0,a02=0,a03=0, a10=0,a11=0,a12=0,a13=0;
            for (int d = 0; d < Hn; d++) {
                const float4 w = *(const float4*)(s_we + d * Hn + c * 4);
                const float t0 = s_tmp[(r * 2 + 0) * Hn + d];
                const float t1 = s_tmp[(r * 2 + 1) * Hn + d];
                a00 += t0 * w.x; a01 += t0 * w.y; a02 += t0 * w.z; a03 += t0 * w.w;
                a10 += t1 * w.x; a11 += t1 * w.y; a12 += t1 * w.z; a13 += t1 * w.w;
            }
            *(float4*)(s_eh + (r * 2 + 0) * Hn + c * 4) = make_float4(a00, a01, a02, a03);
            *(float4*)(s_eh + (r * 2 + 1) * Hn + c * 4) = make_float4(a10, a11, a12, a13);
        }
        __syncthreads();
        {
            const int d = t & 127;
            for (int n = t >> 7; n < Nn; n += 2) {
                float acc = 0.f;
                #pragma unroll
                for (int e = 0; e < En; e++) acc += s_adj[n * En + e] * s_eh[e * Hn + d];
                s_tmp[n * Hn + d] = acc / s_degn[n];
            }
        }
        __syncthreads();
        {
            const int c = t & 31, r = t >> 5;
            float acc[8][4];
            #pragma unroll
            for (int rr = 0; rr < 8; rr++) { acc[rr][0]=0; acc[rr][1]=0; acc[rr][2]=0; acc[rr][3]=0; }
            for (int d = 0; d < Hn; d++) {
                const float4 w = *(const float4*)(s_wn + d * Hn + c * 4);
                #pragma unroll
                for (int rr = 0; rr < 8; rr++) {
                    const float tv = s_tmp[(r * 8 + rr) * Hn + d];
                    acc[rr][0] += tv * w.x; acc[rr][1] += tv * w.y;
                    acc[rr][2] += tv * w.z; acc[rr][3] += tv * w.w;
                }
            }
            #pragma unroll
            for (int rr = 0; rr < 8; rr++)
                *(float4*)(s_nh + (r * 8 + rr) * Hn + c * 4) =
                    make_float4(acc[rr][0], acc[rr][1], acc[rr][2], acc[rr][3]);
        }
        __syncthreads();
    }

    {
        float4* out4 = (float4*)(g_nodes_h + (size_t)b * Nn * Hn);
        const float4* in4 = (const float4*)s_nh;
        for (int i = t; i < Nn * Hn / 4; i += 256) out4[i] = in4[i];
    }
}

// =============================================================================
// Kernel 2: sequence assembly + attention readout. Writes bf16 hi/lo seqnorm.
// =============================================================================
__global__ void __launch_bounds__(256, 1)
attn_kernel(const int* __restrict__ item_seq, const int* __restrict__ alias_item,
            const int* __restrict__ alias_cate,
            const float* __restrict__ q1_w, const float* __restrict__ q1_b,
            const float* __restrict__ q2_w, const float* __restrict__ v_w) {
    extern __shared__ float s_seq[];        // [50][256]
    __shared__ float s_q1[Dn];
    __shared__ float s_mask[64];
    __shared__ float s_red[8];
    __shared__ float s_bcast;
    __shared__ int   s_last;

    const int b = blockIdx.x;
    const int t = threadIdx.x;
    const int lane = t & 31, wid = t >> 5;

    if (t < Ln) s_mask[t] = (item_seq[b * Ln + t] > 0) ? 1.0f : 0.0f;
    if (t == 0) {
        int cnt = 0;
        for (int l = 0; l < Ln; l++) cnt += (item_seq[b * Ln + l] > 0) ? 1 : 0;
        s_last = max(cnt - 1, 0);
    }

    for (int l = wid; l < Ln; l += 8) {
        const int ai = alias_item[b * Ln + l];
        const int ac = alias_cate[b * Ln + l];
        const float4 vi = ((const float4*)(g_nodes_h + ((size_t)b * Nn + ai) * Hn))[lane];
        const float4 vc = ((const float4*)(g_nodes_h + ((size_t)b * Nn + ac) * Hn))[lane];
        float ss = vi.x*vi.x + vi.y*vi.y + vi.z*vi.z + vi.w*vi.w
                 + vc.x*vc.x + vc.y*vc.y + vc.z*vc.z + vc.w*vc.w;
        #pragma unroll
        for (int o = 16; o > 0; o >>= 1) ss += __shfl_xor_sync(0xffffffffu, ss, o);
        const float inv = 1.0f / fmaxf(sqrtf(ss), EPS);
        ((float4*)(s_seq + l * Dn))[lane]      = make_float4(vi.x*inv, vi.y*inv, vi.z*inv, vi.w*inv);
        ((float4*)(s_seq + l * Dn))[lane + 32] = make_float4(vc.x*inv, vc.y*inv, vc.z*inv, vc.w*inv);
    }
    __syncthreads();

    {
        const int last = s_last;
        float acc = 0.f;
        for (int d = 0; d < Dn; d++) acc += s_seq[last * Dn + d] * q1_w[d * Dn + t];
        s_q1[t] = acc + q1_b[t];
    }

    float q2acc[Ln];
    #pragma unroll
    for (int l = 0; l < Ln; l++) q2acc[l] = 0.f;
    for (int d = 0; d < Dn; d++) {
        const float w = q2_w[d * Dn + t];
        #pragma unroll
        for (int l = 0; l < Ln; l++) q2acc[l] += s_seq[l * Dn + d] * w;
    }

    const float vw = v_w[t];
    const float q1v = s_q1[t];
    float outacc = 0.f;
    for (int l = 0; l < Ln; l++) {
        const float x = q1v + q2acc[l];
        const float val = 1.0f / (1.0f + expf(-x));
        float c = val * vw;
        #pragma unroll
        for (int o = 16; o > 0; o >>= 1) c += __shfl_xor_sync(0xffffffffu, c, o);
        if (lane == 0) s_red[wid] = c;
        __syncthreads();
        if (t == 0) {
            float a = 0.f;
            #pragma unroll
            for (int w = 0; w < 8; w++) a += s_red[w];
            s_bcast = a;
        }
        __syncthreads();
        outacc += s_bcast * s_mask[l] * s_seq[l * Dn + t];
    }

    {
        float ss = outacc * outacc;
        #pragma unroll
        for (int o = 16; o > 0; o >>= 1) ss += __shfl_xor_sync(0xffffffffu, ss, o);
        if (lane == 0) s_red[wid] = ss;
        __syncthreads();
        if (t == 0) {
            float a = 0.f;
            #pragma unroll
            for (int w = 0; w < 8; w++) a += s_red[w];
            s_bcast = a;
        }
        __syncthreads();
        const float inv = 1.0f / fmaxf(sqrtf(s_bcast), EPS);
        const float v = outacc * inv;
        const __nv_bfloat16 h = __float2bfloat16_rn(v);
        g_seq_hi[b * Dn + t] = h;
        g_seq_lo[b * Dn + t] = __float2bfloat16_rn(v - __bfloat162float(h));
    }
}

// =============================================================================
// Kernel 3: item_norm split into bf16 hi/lo.
// =============================================================================
__device__ __forceinline__ void store4_hilo(__nv_bfloat16* hi, __nv_bfloat16* lo,
                                            int c, float4 v) {
    __nv_bfloat16 h0 = __float2bfloat16_rn(v.x), h1 = __float2bfloat16_rn(v.y);
    __nv_bfloat16 h2 = __float2bfloat16_rn(v.z), h3 = __float2bfloat16_rn(v.w);
    *(__nv_bfloat162*)(hi + c)     = __halves2bfloat162(h0, h1);
    *(__nv_bfloat162*)(hi + c + 2) = __halves2bfloat162(h2, h3);
    __nv_bfloat16 l0 = __float2bfloat16_rn(v.x - __bfloat162float(h0));
    __nv_bfloat16 l1 = __float2bfloat16_rn(v.y - __bfloat162float(h1));
    __nv_bfloat16 l2 = __float2bfloat16_rn(v.z - __bfloat162float(h2));
    __nv_bfloat16 l3 = __float2bfloat16_rn(v.w - __bfloat162float(h3));
    *(__nv_bfloat162*)(lo + c)     = __halves2bfloat162(l0, l1);
    *(__nv_bfloat162*)(lo + c + 2) = __halves2bfloat162(l2, l3);
}

__global__ void __launch_bounds__(256)
itemnorm_kernel(const float* __restrict__ embedding, const int* __restrict__ item_cates) {
    const int i = blockIdx.x * 8 + (threadIdx.x >> 5);
    const int lane = threadIdx.x & 31;
    if (i >= ITEMN) return;
    const int c = item_cates[i];
    const float4 vi = ((const float4*)(embedding + (size_t)i * Hn))[lane];
    const float4 vc = ((const float4*)(embedding + (size_t)c * Hn))[lane];
    float ss = vi.x*vi.x + vi.y*vi.y + vi.z*vi.z + vi.w*vi.w
             + vc.x*vc.x + vc.y*vc.y + vc.z*vc.z + vc.w*vc.w;
    #pragma unroll
    for (int o = 16; o > 0; o >>= 1) ss += __shfl_xor_sync(0xffffffffu, ss, o);
    const float inv = 1.0f / fmaxf(sqrtf(ss), EPS);
    __nv_bfloat16* hi = g_item_hi + (size_t)i * Dn;
    __nv_bfloat16* lo = g_item_lo + (size_t)i * Dn;
    store4_hilo(hi, lo, lane * 4,
                make_float4(vi.x*inv, vi.y*inv, vi.z*inv, vi.w*inv));
    store4_hilo(hi, lo, 128 + lane * 4,
                make_float4(vc.x*inv, vc.y*inv, vc.z*inv, vc.w*inv));
}

// =============================================================================
// Kernel 4: scores via mma.sync (HMMA) split-bf16.
//   C[b][i] = 16 * (Ahi·Bhi + Ahi·Blo + Alo·Bhi)[i][b]
// CTA tile: 128 items (M) x 128 batch (N), K=256 in 8 chunks of 32,
// cp.async double-buffered. 8 warps: warp_m = w&3 (32 rows), warp_n = w>>2 (64 cols).
// smem rows: 80B stride (32 bf16 + 16B pad) -> conflict-free ldmatrix.
// =============================================================================
#define ROWB 80
#define MATB (128 * ROWB)          // 10240 bytes per matrix
#define BUFB (4 * MATB)            // 40960 per buffer
#define SC_SMEM (2 * BUFB)         // 81920

__global__ void __launch_bounds__(256)
scores_mma(float* __restrict__ C) {
    extern __shared__ char smc[];
    const uint32_t sb = smem_u32(smc);

    const int t = threadIdx.x;
    const int w = t >> 5, lane = t & 31;
    const int b0 = blockIdx.x * 128;   // batch tile (fastest -> L2 reuse of A)
    const int i0 = blockIdx.y * 128;   // item tile
    const int warp_m = w & 3;          // 0..3 -> 32 item rows each
    const int warp_n = w >> 2;         // 0..1 -> 64 batch cols each

    const __nv_bfloat16* srcs[4] = {
        g_item_hi + (size_t)i0 * Dn, g_item_lo + (size_t)i0 * Dn,
        g_seq_hi  + (size_t)b0 * Dn, g_seq_lo  + (size_t)b0 * Dn
    };

    // per-thread load coords: 2 segs per matrix per chunk
    const int ld_row0 = t >> 2,  ld_seg0 = t & 3;          // e = t
    const int ld_row1 = (256 + t) >> 2, ld_seg1 = t & 3;   // e = 256 + t

    float acc[2][8][4];
    #pragma unroll
    for (int i = 0; i < 2; i++)
        #pragma unroll
        for (int j = 0; j < 8; j++)
            #pragma unroll
            for (int r = 0; r < 4; r++) acc[i][j][r] = 0.f;

    // lane components of ldmatrix addresses
    const uint32_t aA_lane = (uint32_t)((lane & 15) * ROWB + (lane >> 4) * 16);
    const uint32_t aB_lane = (uint32_t)(((lane & 7) + ((lane >> 4) & 1) * 8) * ROWB
                                        + ((lane >> 3) & 1) * 16);

    // prefetch chunk 0 -> buffer 0
    #pragma unroll
    for (int mat = 0; mat < 4; mat++) {
        cp16(sb + 0 * BUFB + mat * MATB + ld_row0 * ROWB + ld_seg0 * 16,
             srcs[mat] + ld_row0 * Dn + 0 + ld_seg0 * 8);
        cp16(sb + 0 * BUFB + mat * MATB + ld_row1 * ROWB + ld_seg1 * 16,
             srcs[mat] + ld_row1 * Dn + 0 + ld_seg1 * 8);
    }
    CP_COMMIT();

    for (int kc = 0; kc < 8; kc++) {
        const int buf = kc & 1;
        if (kc < 7) {
            const int k0 = (kc + 1) * 32;
            const int nbuf = (kc + 1) & 1;
            #pragma unroll
            for (int mat = 0; mat < 4; mat++) {
                cp16(sb + nbuf * BUFB + mat * MATB + ld_row0 * ROWB + ld_seg0 * 16,
                     srcs[mat] + ld_row0 * Dn + k0 + ld_seg0 * 8);
                cp16(sb + nbuf * BUFB + mat * MATB + ld_row1 * ROWB + ld_seg1 * 16,
                     srcs[mat] + ld_row1 * Dn + k0 + ld_seg1 * 8);
            }
            CP_COMMIT();
            CP_WAIT(1);
        } else {
            CP_WAIT(0);
        }
        __syncthreads();

        const uint32_t baseA = sb + buf * BUFB + (uint32_t)(warp_m * 32) * ROWB + aA_lane;
        const uint32_t baseB = sb + buf * BUFB + (uint32_t)(warp_n * 64) * ROWB + aB_lane;

        #pragma unroll
        for (int ks = 0; ks < 2; ks++) {
            const uint32_t koff = (uint32_t)ks * 32;
            uint32_t ahi[2][4], alo[2][4];
            #pragma unroll
            for (int i = 0; i < 2; i++) {
                ldsm4(ahi[i], baseA + 0 * MATB + (uint32_t)(i * 16) * ROWB + koff);
                ldsm4(alo[i], baseA + 1 * MATB + (uint32_t)(i * 16) * ROWB + koff);
            }
            uint32_t bhi[4][4], blo[4][4];
            #pragma unroll
            for (int j4 = 0; j4 < 4; j4++) {
                ldsm4(bhi[j4], baseB + 2 * MATB + (uint32_t)(j4 * 16) * ROWB + koff);
                ldsm4(blo[j4], baseB + 3 * MATB + (uint32_t)(j4 * 16) * ROWB + koff);
            }
            #pragma unroll
            for (int i = 0; i < 2; i++)
                #pragma unroll
                for (int j = 0; j < 8; j++) {
                    const uint32_t* bh = &bhi[j >> 1][(j & 1) * 2];
                    const uint32_t* bl = &blo[j >> 1][(j & 1) * 2];
                    mma16816(acc[i][j], ahi[i], bh);
                    mma16816(acc[i][j], ahi[i], bl);
                    mma16816(acc[i][j], alo[i], bh);
                }
        }
        __syncthreads();
    }

    // epilogue: C[batch][item]
    const int mrow = i0 + warp_m * 32 + (lane >> 2);     // +{0,8} and +{0,16}
    const int ncol = b0 + warp_n * 64 + (lane & 3) * 2;  // +{0,1} and j*8
    #pragma unroll
    for (int i = 0; i < 2; i++) {
        #pragma unroll
        for (int j = 0; j < 8; j++) {
            const int n = ncol + j * 8;
            const int m = mrow + i * 16;
            if (m < ITEMN) {
                C[(size_t)n       * ITEMN + m]     = 16.f * acc[i][j][0];
                C[(size_t)(n + 1) * ITEMN + m]     = 16.f * acc[i][j][1];
            }
            if (m + 8 < ITEMN) {
                C[(size_t)n       * ITEMN + m + 8] = 16.f * acc[i][j][2];
                C[(size_t)(n + 1) * ITEMN + m + 8] = 16.f * acc[i][j][3];
            }
        }
    }
}

// =============================================================================
// launch
// =============================================================================
extern "C" void kernel_launch(void* const* d_in, const int* in_sizes, int n_in,
                              void* d_out, int out_size) {
    const int*   item_seq   = (const int*)  d_in[0];
    /* label d_in[1] unused */
    const int*   nodes      = (const int*)  d_in[2];
    const float* hn_adj     = (const float*)d_in[3];
    const int*   alias_item = (const int*)  d_in[4];
    const int*   alias_cate = (const int*)  d_in[5];
    const float* embedding  = (const float*)d_in[6];
    const int*   item_cates = (const int*)  d_in[7];
    const float* w_edge     = (const float*)d_in[8];
    const float* w_node     = (const float*)d_in[9];
    const float* q1_w       = (const float*)d_in[10];
    const float* q1_b       = (const float*)d_in[11];
    const float* q2_w       = (const float*)d_in[12];
    const float* v_w        = (const float*)d_in[13];
    float* out = (float*)d_out;

    const int hg_smem  = (16384 + 16384 + 8192 + 8192 + 2048 + 1024 + 16 + 64 + 64) * 4;
    const int seq_smem = Ln * Dn * 4;
    cudaFuncSetAttribute(hgnn_kernel, cudaFuncAttributeMaxDynamicSharedMemorySize, hg_smem);
    cudaFuncSetAttribute(attn_kernel, cudaFuncAttributeMaxDynamicSharedMemorySize, seq_smem);
    cudaFuncSetAttribute(scores_mma, cudaFuncAttributeMaxDynamicSharedMemorySize, SC_SMEM);

    hgnn_kernel<<<Bn, 256, hg_smem>>>(nodes, hn_adj, embedding, w_edge, w_node);
    attn_kernel<<<Bn, 256, seq_smem>>>(item_seq, alias_item, alias_cate, q1_w, q1_b, q2_w, v_w);
    itemnorm_kernel<<<(ITEMN + 7) / 8, 256>>>(embedding, item_cates);
    scores_mma<<<dim3(4, ITEMP / 128), 256, SC_SMEM>>>(out);
}

// round 4
// speedup vs baseline: 1.5297x; 1.1485x over previous
#include <cuda_runtime.h>
#include <cuda_bf16.h>
#include <math.h>
#include <stdint.h>

#define Bn 512
#define Ln 50
#define Nn 64
#define En 16
#define Hn 128
#define Dn 256
#define ITEMN 100000
#define ITEMP 100096   // padded to multiple of 128
#define EPS 1e-12f
#define SP 136         // padded smem row stride (floats) for hgnn

// ------------------------- scratch (no allocs allowed) -------------------------
__device__ float g_nodes_h[Bn * Nn * Hn];                    // 16.8 MB
__device__ __nv_bfloat16 g_item_hi[(size_t)ITEMP * Dn];      // 51.2 MB
__device__ __nv_bfloat16 g_item_lo[(size_t)ITEMP * Dn];      // 51.2 MB
__device__ __nv_bfloat16 g_seq_hi[Bn * Dn];
__device__ __nv_bfloat16 g_seq_lo[Bn * Dn];

// ============================= PTX helpers =============================
__device__ __forceinline__ uint32_t smem_u32(const void* p) {
    uint32_t a;
    asm("{ .reg .u64 t; cvta.to.shared.u64 t, %1; cvt.u32.u64 %0, t; }" : "=r"(a) : "l"(p));
    return a;
}
__device__ __forceinline__ void cp16(uint32_t dst, const void* src) {
    asm volatile("cp.async.cg.shared.global [%0], [%1], 16;" :: "r"(dst), "l"(src));
}
#define CP_COMMIT() asm volatile("cp.async.commit_group;" ::: "memory")
#define CP_WAIT(n)  asm volatile("cp.async.wait_group %0;" :: "n"(n) : "memory")

__device__ __forceinline__ void ldsm4(uint32_t* r, uint32_t addr) {
    asm volatile("ldmatrix.sync.aligned.m8n8.x4.shared.b16 {%0,%1,%2,%3}, [%4];"
                 : "=r"(r[0]), "=r"(r[1]), "=r"(r[2]), "=r"(r[3]) : "r"(addr));
}
__device__ __forceinline__ void mma16816(float* d, const uint32_t* a, const uint32_t* b) {
    asm volatile(
        "mma.sync.aligned.m16n8k16.row.col.f32.bf16.bf16.f32 "
        "{%0,%1,%2,%3}, {%4,%5,%6,%7}, {%8,%9}, {%0,%1,%2,%3};"
        : "+f"(d[0]), "+f"(d[1]), "+f"(d[2]), "+f"(d[3])
        : "r"(a[0]), "r"(a[1]), "r"(a[2]), "r"(a[3]), "r"(b[0]), "r"(b[1]));
}

// =============================================================================
// Kernel 1: per-batch hypergraph GNN. One CTA per batch.
// Weights streamed from L2 (read once per CTA per GEMM via per-warp column
// slices); smem holds only activations (padded stride SP) -> 2 CTAs/SM.
// =============================================================================
__global__ void __launch_bounds__(256, 2)
hgnn_kernel(const int* __restrict__ nodes, const float* __restrict__ hn_adj,
            const float* __restrict__ embedding,
            const float* __restrict__ w_edge, const float* __restrict__ w_node) {
    extern __shared__ float sm[];
    float* s_nh   = sm;                         // 64*SP
    float* s_tmp  = s_nh  + 64 * SP;            // 64*SP
    float* s_eh   = s_tmp + 64 * SP;            // 16*SP
    float* s_adj  = s_eh  + 16 * SP;            // 1024
    float* s_dege = s_adj + 1024;               // 16
    float* s_degn = s_dege + 16;                // 64
    int*   s_idx  = (int*)(s_degn + 64);        // 64

    const int b = blockIdx.x;
    const int t = threadIdx.x;
    const int lane = t & 31, wid = t >> 5;

    {
        const float* adjb = hn_adj + (size_t)b * Nn * En;
        for (int i = t; i < Nn * En; i += 256) s_adj[i] = adjb[i];
        if (t < Nn) s_idx[t] = nodes[b * Nn + t];
    }
    __syncthreads();

    if (t < En) {
        float s = 0.f;
        #pragma unroll 8
        for (int n = 0; n < Nn; n++) s += s_adj[n * En + t];
        s_dege[t] = fmaxf(s, 1.0f);
    }
    if (t >= 32 && t < 32 + Nn) {
        int n = t - 32;
        float s = 0.f;
        #pragma unroll
        for (int e = 0; e < En; e++) s += s_adj[n * En + e];
        s_degn[n] = fmaxf(s, 1.0f);
    }

    // init n_h = l2norm(embedding[nodes]) — warp per row
    for (int n = wid; n < Nn; n += 8) {
        const float4 v = ((const float4*)(embedding + (size_t)s_idx[n] * Hn))[lane];
        float ss = v.x * v.x + v.y * v.y + v.z * v.z + v.w * v.w;
        #pragma unroll
        for (int o = 16; o > 0; o >>= 1) ss += __shfl_xor_sync(0xffffffffu, ss, o);
        const float inv = 1.0f / fmaxf(sqrtf(ss), EPS);
        ((float4*)(s_nh + n * SP))[lane] = make_float4(v.x * inv, v.y * inv, v.z * inv, v.w * inv);
    }
    __syncthreads();

    // per-warp output column slice for the GEMMs
    const int cw = wid * 16 + (lane & 3) * 4;   // 4 output cols (float4)
    const int rg = lane >> 2;                   // row group 0..7

    for (int step = 0; step < 2; step++) {
        // agg_e[e,d] = (sum_n adj[n,e] * n_h[n,d]) / deg_e[e]  -> s_tmp rows 0..15
        {
            const int d = t & 127;
            for (int e = t >> 7; e < En; e += 2) {
                float acc = 0.f;
                #pragma unroll 8
                for (int n = 0; n < Nn; n++) acc += s_adj[n * En + e] * s_nh[n * SP + d];
                s_tmp[e * SP + d] = acc / s_dege[e];
            }
        }
        __syncthreads();
        // e_h = agg_e @ w_edge (16x128 @ 128x128): lane does rows {rg, rg+8} x cols cw..cw+3
        {
            float4 a0 = make_float4(0.f,0.f,0.f,0.f), a1 = make_float4(0.f,0.f,0.f,0.f);
            #pragma unroll 4
            for (int d = 0; d < Hn; d++) {
                const float4 wv = __ldg((const float4*)(w_edge + d * Hn + cw));
                const float t0 = s_tmp[rg * SP + d];
                const float t1 = s_tmp[(rg + 8) * SP + d];
                a0.x += t0 * wv.x; a0.y += t0 * wv.y; a0.z += t0 * wv.z; a0.w += t0 * wv.w;
                a1.x += t1 * wv.x; a1.y += t1 * wv.y; a1.z += t1 * wv.z; a1.w += t1 * wv.w;
            }
            *(float4*)(s_eh + rg * SP + cw)       = a0;
            *(float4*)(s_eh + (rg + 8) * SP + cw) = a1;
        }
        __syncthreads();
        // agg_n[n,d] = (sum_e adj[n,e] * e_h[e,d]) / deg_n[n]  -> s_tmp rows 0..63
        {
            const int d = t & 127;
            for (int n = t >> 7; n < Nn; n += 2) {
                float acc = 0.f;
                #pragma unroll
                for (int e = 0; e < En; e++) acc += s_adj[n * En + e] * s_eh[e * SP + d];
                s_tmp[n * SP + d] = acc / s_degn[n];
            }
        }
        __syncthreads();
        // n_h = agg_n @ w_node (64x128 @ 128x128): lane rows {rg+8k} x cols cw..cw+3
        {
            float acc[8][4];
            #pragma unroll
            for (int k = 0; k < 8; k++) { acc[k][0]=0; acc[k][1]=0; acc[k][2]=0; acc[k][3]=0; }
            #pragma unroll 4
            for (int d = 0; d < Hn; d++) {
                const float4 wv = __ldg((const float4*)(w_node + d * Hn + cw));
                #pragma unroll
                for (int k = 0; k < 8; k++) {
                    const float tv = s_tmp[(rg + 8 * k) * SP + d];
                    acc[k][0] += tv * wv.x; acc[k][1] += tv * wv.y;
                    acc[k][2] += tv * wv.z; acc[k][3] += tv * wv.w;
                }
            }
            #pragma unroll
            for (int k = 0; k < 8; k++)
                *(float4*)(s_nh + (rg + 8 * k) * SP + cw) =
                    make_float4(acc[k][0], acc[k][1], acc[k][2], acc[k][3]);
        }
        __syncthreads();
    }

    // write final node hidden (compact stride Hn)
    {
        float4* out4 = (float4*)(g_nodes_h + (size_t)b * Nn * Hn);
        for (int f = t; f < Nn * Hn / 4; f += 256) {
            const int row = f >> 5, c4 = f & 31;
            out4[f] = *(const float4*)(s_nh + row * SP + c4 * 4);
        }
    }
}

// =============================================================================
// Kernel 2: sequence assembly + attention readout (2 barriers for alpha,
// not 100). Writes bf16 hi/lo seqnorm.
// =============================================================================
__global__ void __launch_bounds__(256, 1)
attn_kernel(const int* __restrict__ item_seq, const int* __restrict__ alias_item,
            const int* __restrict__ alias_cate,
            const float* __restrict__ q1_w, const float* __restrict__ q1_b,
            const float* __restrict__ q2_w, const float* __restrict__ v_w) {
    extern __shared__ float s_seq[];        // [50][256]
    __shared__ float s_part[Ln * 8];
    __shared__ float s_alpha[Ln];
    __shared__ float s_mask[64];
    __shared__ float s_red[8];
    __shared__ float s_bcast;
    __shared__ int   s_last;

    const int b = blockIdx.x;
    const int t = threadIdx.x;
    const int lane = t & 31, wid = t >> 5;

    if (t < Ln) s_mask[t] = (item_seq[b * Ln + t] > 0) ? 1.0f : 0.0f;
    if (t == 0) {
        int cnt = 0;
        for (int l = 0; l < Ln; l++) cnt += (item_seq[b * Ln + l] > 0) ? 1 : 0;
        s_last = max(cnt - 1, 0);
    }

    for (int l = wid; l < Ln; l += 8) {
        const int ai = alias_item[b * Ln + l];
        const int ac = alias_cate[b * Ln + l];
        const float4 vi = ((const float4*)(g_nodes_h + ((size_t)b * Nn + ai) * Hn))[lane];
        const float4 vc = ((const float4*)(g_nodes_h + ((size_t)b * Nn + ac) * Hn))[lane];
        float ss = vi.x*vi.x + vi.y*vi.y + vi.z*vi.z + vi.w*vi.w
                 + vc.x*vc.x + vc.y*vc.y + vc.z*vc.z + vc.w*vc.w;
        #pragma unroll
        for (int o = 16; o > 0; o >>= 1) ss += __shfl_xor_sync(0xffffffffu, ss, o);
        const float inv = 1.0f / fmaxf(sqrtf(ss), EPS);
        ((float4*)(s_seq + l * Dn))[lane]      = make_float4(vi.x*inv, vi.y*inv, vi.z*inv, vi.w*inv);
        ((float4*)(s_seq + l * Dn))[lane + 32] = make_float4(vc.x*inv, vc.y*inv, vc.z*inv, vc.w*inv);
    }
    __syncthreads();

    // q1v = (ht @ q1_w + q1_b)[t]  (stays in register)
    float q1v;
    {
        const int last = s_last;
        float acc = 0.f;
        for (int d = 0; d < Dn; d++) acc += s_seq[last * Dn + d] * q1_w[d * Dn + t];
        q1v = acc + q1_b[t];
    }

    // q2[l][t] in registers
    float q2acc[Ln];
    #pragma unroll
    for (int l = 0; l < Ln; l++) q2acc[l] = 0.f;
    for (int d = 0; d < Dn; d++) {
        const float w = q2_w[d * Dn + t];
        #pragma unroll
        for (int l = 0; l < Ln; l++) q2acc[l] += s_seq[l * Dn + d] * w;
    }

    // alpha[l] = sum_t sigmoid(q1[t]+q2[l][t]) * vw[t]  (warp reduce + 2 barriers)
    const float vw = v_w[t];
    #pragma unroll
    for (int l = 0; l < Ln; l++) {
        const float x = q1v + q2acc[l];
        float c = vw / (1.0f + expf(-x));
        #pragma unroll
        for (int o = 16; o > 0; o >>= 1) c += __shfl_xor_sync(0xffffffffu, c, o);
        if (lane == 0) s_part[l * 8 + wid] = c;
    }
    __syncthreads();
    if (t < Ln) {
        float a = 0.f;
        #pragma unroll
        for (int w = 0; w < 8; w++) a += s_part[t * 8 + w];
        s_alpha[t] = a * s_mask[t];
    }
    __syncthreads();

    // out[t] = sum_l alpha[l] * seq[l][t]
    float outacc = 0.f;
    #pragma unroll
    for (int l = 0; l < Ln; l++) outacc += s_alpha[l] * s_seq[l * Dn + t];

    // l2norm(seq_output) -> bf16 hi/lo
    {
        float ss = outacc * outacc;
        #pragma unroll
        for (int o = 16; o > 0; o >>= 1) ss += __shfl_xor_sync(0xffffffffu, ss, o);
        if (lane == 0) s_red[wid] = ss;
        __syncthreads();
        if (t == 0) {
            float a = 0.f;
            #pragma unroll
            for (int w = 0; w < 8; w++) a += s_red[w];
            s_bcast = a;
        }
        __syncthreads();
        const float inv = 1.0f / fmaxf(sqrtf(s_bcast), EPS);
        const float v = outacc * inv;
        const __nv_bfloat16 h = __float2bfloat16_rn(v);
        g_seq_hi[b * Dn + t] = h;
        g_seq_lo[b * Dn + t] = __float2bfloat16_rn(v - __bfloat162float(h));
    }
}

// =============================================================================
// Kernel 3: item_norm split into bf16 hi/lo.
// =============================================================================
__device__ __forceinline__ void store4_hilo(__nv_bfloat16* hi, __nv_bfloat16* lo,
                                            int c, float4 v) {
    __nv_bfloat16 h0 = __float2bfloat16_rn(v.x), h1 = __float2bfloat16_rn(v.y);
    __nv_bfloat16 h2 = __float2bfloat16_rn(v.z), h3 = __float2bfloat16_rn(v.w);
    *(__nv_bfloat162*)(hi + c)     = __halves2bfloat162(h0, h1);
    *(__nv_bfloat162*)(hi + c + 2) = __halves2bfloat162(h2, h3);
    __nv_bfloat16 l0 = __float2bfloat16_rn(v.x - __bfloat162float(h0));
    __nv_bfloat16 l1 = __float2bfloat16_rn(v.y - __bfloat162float(h1));
    __nv_bfloat16 l2 = __float2bfloat16_rn(v.z - __bfloat162float(h2));
    __nv_bfloat16 l3 = __float2bfloat16_rn(v.w - __bfloat162float(h3));
    *(__nv_bfloat162*)(lo + c)     = __halves2bfloat162(l0, l1);
    *(__nv_bfloat162*)(lo + c + 2) = __halves2bfloat162(l2, l3);
}

__global__ void __launch_bounds__(256)
itemnorm_kernel(const float* __restrict__ embedding, const int* __restrict__ item_cates) {
    const int i = blockIdx.x * 8 + (threadIdx.x >> 5);
    const int lane = threadIdx.x & 31;
    if (i >= ITEMN) return;
    const int c = item_cates[i];
    const float4 vi = ((const float4*)(embedding + (size_t)i * Hn))[lane];
    const float4 vc = ((const float4*)(embedding + (size_t)c * Hn))[lane];
    float ss = vi.x*vi.x + vi.y*vi.y + vi.z*vi.z + vi.w*vi.w
             + vc.x*vc.x + vc.y*vc.y + vc.z*vc.z + vc.w*vc.w;
    #pragma unroll
    for (int o = 16; o > 0; o >>= 1) ss += __shfl_xor_sync(0xffffffffu, ss, o);
    const float inv = 1.0f / fmaxf(sqrtf(ss), EPS);
    __nv_bfloat16* hi = g_item_hi + (size_t)i * Dn;
    __nv_bfloat16* lo = g_item_lo + (size_t)i * Dn;
    store4_hilo(hi, lo, lane * 4,
                make_float4(vi.x*inv, vi.y*inv, vi.z*inv, vi.w*inv));
    store4_hilo(hi, lo, 128 + lane * 4,
                make_float4(vc.x*inv, vc.y*inv, vc.z*inv, vc.w*inv));
}

// =============================================================================
// Kernel 4: scores via mma.sync (HMMA) split-bf16, 2 CTAs/SM.
// =============================================================================
#define ROWB 80
#define MATB (128 * ROWB)          // 10240 bytes per matrix
#define BUFB (4 * MATB)            // 40960 per buffer
#define SC_SMEM (2 * BUFB)         // 81920

__global__ void __launch_bounds__(256, 2)
scores_mma(float* __restrict__ C) {
    extern __shared__ char smc[];
    const uint32_t sb = smem_u32(smc);

    const int t = threadIdx.x;
    const int w = t >> 5, lane = t & 31;
    const int b0 = blockIdx.x * 128;   // batch tile (fastest -> L2 reuse of A)
    const int i0 = blockIdx.y * 128;   // item tile
    const int warp_m = w & 3;          // 0..3 -> 32 item rows each
    const int warp_n = w >> 2;         // 0..1 -> 64 batch cols each

    const __nv_bfloat16* srcs[4] = {
        g_item_hi + (size_t)i0 * Dn, g_item_lo + (size_t)i0 * Dn,
        g_seq_hi  + (size_t)b0 * Dn, g_seq_lo  + (size_t)b0 * Dn
    };

    const int ld_row0 = t >> 2,  ld_seg0 = t & 3;
    const int ld_row1 = (256 + t) >> 2, ld_seg1 = t & 3;

    float acc[2][8][4];
    #pragma unroll
    for (int i = 0; i < 2; i++)
        #pragma unroll
        for (int j = 0; j < 8; j++)
            #pragma unroll
            for (int r = 0; r < 4; r++) acc[i][j][r] = 0.f;

    const uint32_t aA_lane = (uint32_t)((lane & 15) * ROWB + (lane >> 4) * 16);
    const uint32_t aB_lane = (uint32_t)(((lane & 7) + ((lane >> 4) & 1) * 8) * ROWB
                                        + ((lane >> 3) & 1) * 16);

    #pragma unroll
    for (int mat = 0; mat < 4; mat++) {
        cp16(sb + 0 * BUFB + mat * MATB + ld_row0 * ROWB + ld_seg0 * 16,
             srcs[mat] + ld_row0 * Dn + 0 + ld_seg0 * 8);
        cp16(sb + 0 * BUFB + mat * MATB + ld_row1 * ROWB + ld_seg1 * 16,
             srcs[mat] + ld_row1 * Dn + 0 + ld_seg1 * 8);
    }
    CP_COMMIT();

    for (int kc = 0; kc < 8; kc++) {
        const int buf = kc & 1;
        if (kc < 7) {
            const int k0 = (kc + 1) * 32;
            const int nbuf = (kc + 1) & 1;
            #pragma unroll
            for (int mat = 0; mat < 4; mat++) {
                cp16(sb + nbuf * BUFB + mat * MATB + ld_row0 * ROWB + ld_seg0 * 16,
                     srcs[mat] + ld_row0 * Dn + k0 + ld_seg0 * 8);
                cp16(sb + nbuf * BUFB + mat * MATB + ld_row1 * ROWB + ld_seg1 * 16,
                     srcs[mat] + ld_row1 * Dn + k0 + ld_seg1 * 8);
            }
            CP_COMMIT();
            CP_WAIT(1);
        } else {
            CP_WAIT(0);
        }
        __syncthreads();

        const uint32_t baseA = sb + buf * BUFB + (uint32_t)(warp_m * 32) * ROWB + aA_lane;
        const uint32_t baseB = sb + buf * BUFB + (uint32_t)(warp_n * 64) * ROWB + aB_lane;

        #pragma unroll
        for (int ks = 0; ks < 2; ks++) {
            const uint32_t koff = (uint32_t)ks * 32;
            uint32_t ahi[2][4], alo[2][4];
            #pragma unroll
            for (int i = 0; i < 2; i++) {
                ldsm4(ahi[i], baseA + 0 * MATB + (uint32_t)(i * 16) * ROWB + koff);
                ldsm4(alo[i], baseA + 1 * MATB + (uint32_t)(i * 16) * ROWB + koff);
            }
            #pragma unroll
            for (int jg = 0; jg < 2; jg++) {           // 2 j-groups of 32 cols
                uint32_t bhi[2][4], blo[2][4];
                #pragma unroll
                for (int j4 = 0; j4 < 2; j4++) {
                    const uint32_t off = (uint32_t)((jg * 2 + j4) * 16) * ROWB + koff;
                    ldsm4(bhi[j4], baseB + 2 * MATB + off);
                    ldsm4(blo[j4], baseB + 3 * MATB + off);
                }
                #pragma unroll
                for (int i = 0; i < 2; i++)
                    #pragma unroll
                    for (int jj = 0; jj < 4; jj++) {
                        const int j = jg * 4 + jj;
                        const uint32_t* bh = &bhi[jj >> 1][(jj & 1) * 2];
                        const uint32_t* bl = &blo[jj >> 1][(jj & 1) * 2];
                        mma16816(acc[i][j], ahi[i], bh);
                        mma16816(acc[i][j], ahi[i], bl);
                        mma16816(acc[i][j], alo[i], bh);
                    }
            }
        }
        __syncthreads();
    }

    // epilogue: C[batch][item]
    const int mrow = i0 + warp_m * 32 + (lane >> 2);
    const int ncol = b0 + warp_n * 64 + (lane & 3) * 2;
    #pragma unroll
    for (int i = 0; i < 2; i++) {
        #pragma unroll
        for (int j = 0; j < 8; j++) {
            const int n = ncol + j * 8;
            const int m = mrow + i * 16;
            if (m < ITEMN) {
                C[(size_t)n       * ITEMN + m]     = 16.f * acc[i][j][0];
                C[(size_t)(n + 1) * ITEMN + m]     = 16.f * acc[i][j][1];
            }
            if (m + 8 < ITEMN) {
                C[(size_t)n       * ITEMN + m + 8] = 16.f * acc[i][j][2];
                C[(size_t)(n + 1) * ITEMN + m + 8] = 16.f * acc[i][j][3];
            }
        }
    }
}

// =============================================================================
// launch
// =============================================================================
extern "C" void kernel_launch(void* const* d_in, const int* in_sizes, int n_in,
                              void* d_out, int out_size) {
    const int*   item_seq   = (const int*)  d_in[0];
    /* label d_in[1] unused */
    const int*   nodes      = (const int*)  d_in[2];
    const float* hn_adj     = (const float*)d_in[3];
    const int*   alias_item = (const int*)  d_in[4];
    const int*   alias_cate = (const int*)  d_in[5];
    const float* embedding  = (const float*)d_in[6];
    const int*   item_cates = (const int*)  d_in[7];
    const float* w_edge     = (const float*)d_in[8];
    const float* w_node     = (const float*)d_in[9];
    const float* q1_w       = (const float*)d_in[10];
    const float* q1_b       = (const float*)d_in[11];
    const float* q2_w       = (const float*)d_in[12];
    const float* v_w        = (const float*)d_in[13];
    float* out = (float*)d_out;

    const int hg_smem  = (64 * SP + 64 * SP + 16 * SP + 1024 + 16 + 64 + 64) * 4;
    const int seq_smem = Ln * Dn * 4;
    cudaFuncSetAttribute(hgnn_kernel, cudaFuncAttributeMaxDynamicSharedMemorySize, hg_smem);
    cudaFuncSetAttribute(attn_kernel, cudaFuncAttributeMaxDynamicSharedMemorySize, seq_smem);
    cudaFuncSetAttribute(scores_mma, cudaFuncAttributeMaxDynamicSharedMemorySize, SC_SMEM);

    hgnn_kernel<<<Bn, 256, hg_smem>>>(nodes, hn_adj, embedding, w_edge, w_node);
    attn_kernel<<<Bn, 256, seq_smem>>>(item_seq, alias_item, alias_cate, q1_w, q1_b, q2_w, v_w);
    itemnorm_kernel<<<(ITEMN + 7) / 8, 256>>>(embedding, item_cates);
    scores_mma<<<dim3(4, ITEMP / 128), 256, SC_SMEM>>>(out);
}

// round 7
// speedup vs baseline: 1.8122x; 1.1847x over previous
#include <cuda_runtime.h>
#include <cuda_bf16.h>
#include <math.h>
#include <stdint.h>

#define Bn 512
#define Ln 50
#define Nn 64
#define En 16
#define Hn 128
#define Dn 256
#define ITEMN 100000
#define ITEMP 100096
#define EPS 1e-12f
#define SP 136         // padded smem row stride (floats) for hgnn

// ------------------------- scratch (no allocs allowed) -------------------------
__device__ float g_nodes_h[Bn * Nn * Hn];                    // 16.8 MB
__device__ float g_seq_f32[25600 * 256];                     // 26.2 MB
__device__ float g_q2[25600 * 256];                          // 26.2 MB
__device__ float g_q2t_f32[256 * 256];                       // 0.25 MB (q2_w^T)
__device__ __nv_bfloat16 g_so_hi[Bn * Dn], g_so_lo[Bn * Dn];
__device__ __nv_bfloat16 g_item_hi[(size_t)ITEMP * Dn];      // 51.2 MB
__device__ __nv_bfloat16 g_item_lo[(size_t)ITEMP * Dn];      // 51.2 MB

// ============================= PTX helpers =============================
__device__ __forceinline__ uint32_t smem_u32(const void* p) {
    uint32_t a;
    asm("{ .reg .u64 t; cvta.to.shared.u64 t, %1; cvt.u32.u64 %0, t; }" : "=r"(a) : "l"(p));
    return a;
}
__device__ __forceinline__ void cp16(uint32_t dst, const void* src) {
    asm volatile("cp.async.cg.shared.global [%0], [%1], 16;" :: "r"(dst), "l"(src));
}
#define CP_COMMIT() asm volatile("cp.async.commit_group;" ::: "memory")
#define CP_WAIT(n)  asm volatile("cp.async.wait_group %0;" :: "n"(n) : "memory")

__device__ __forceinline__ void ldsm4(uint32_t* r, uint32_t addr) {
    asm volatile("ldmatrix.sync.aligned.m8n8.x4.shared.b16 {%0,%1,%2,%3}, [%4];"
                 : "=r"(r[0]), "=r"(r[1]), "=r"(r[2]), "=r"(r[3]) : "r"(addr));
}
__device__ __forceinline__ void mma16816(float* d, const uint32_t* a, const uint32_t* b) {
    asm volatile(
        "mma.sync.aligned.m16n8k16.row.col.f32.bf16.bf16.f32 "
        "{%0,%1,%2,%3}, {%4,%5,%6,%7}, {%8,%9}, {%0,%1,%2,%3};"
        : "+f"(d[0]), "+f"(d[1]), "+f"(d[2]), "+f"(d[3])
        : "r"(a[0]), "r"(a[1]), "r"(a[2]), "r"(a[3]), "r"(b[0]), "r"(b[1]));
}
__device__ __forceinline__ void sthilo(__nv_bfloat16* hi, __nv_bfloat16* lo,
                                       size_t idx, float v) {
    __nv_bfloat16 h = __float2bfloat16_rn(v);
    hi[idx] = h;
    lo[idx] = __float2bfloat16_rn(v - __bfloat162float(h));
}
__device__ __forceinline__ void store4_hilo(__nv_bfloat16* hi, __nv_bfloat16* lo,
                                            int c, float4 v) {
    __nv_bfloat16 h0 = __float2bfloat16_rn(v.x), h1 = __float2bfloat16_rn(v.y);
    __nv_bfloat16 h2 = __float2bfloat16_rn(v.z), h3 = __float2bfloat16_rn(v.w);
    *(__nv_bfloat162*)(hi + c)     = __halves2bfloat162(h0, h1);
    *(__nv_bfloat162*)(hi + c + 2) = __halves2bfloat162(h2, h3);
    __nv_bfloat16 l0 = __float2bfloat16_rn(v.x - __bfloat162float(h0));
    __nv_bfloat16 l1 = __float2bfloat16_rn(v.y - __bfloat162float(h1));
    __nv_bfloat16 l2 = __float2bfloat16_rn(v.z - __bfloat162float(h2));
    __nv_bfloat16 l3 = __float2bfloat16_rn(v.w - __bfloat162float(h3));
    *(__nv_bfloat162*)(lo + c)     = __halves2bfloat162(l0, l1);
    *(__nv_bfloat162*)(lo + c + 2) = __halves2bfloat162(l2, l3);
}

// =============================================================================
// Kernel 1: per-batch hypergraph GNN (R4 PROVEN — unchanged).
// =============================================================================
__global__ void __launch_bounds__(256, 2)
hgnn_kernel(const int* __restrict__ nodes, const float* __restrict__ hn_adj,
            const float* __restrict__ embedding,
            const float* __restrict__ w_edge, const float* __restrict__ w_node) {
    extern __shared__ float sm[];
    float* s_nh   = sm;
    float* s_tmp  = s_nh  + 64 * SP;
    float* s_eh   = s_tmp + 64 * SP;
    float* s_adj  = s_eh  + 16 * SP;
    float* s_dege = s_adj + 1024;
    float* s_degn = s_dege + 16;
    int*   s_idx  = (int*)(s_degn + 64);

    const int b = blockIdx.x;
    const int t = threadIdx.x;
    const int lane = t & 31, wid = t >> 5;

    {
        const float* adjb = hn_adj + (size_t)b * Nn * En;
        for (int i = t; i < Nn * En; i += 256) s_adj[i] = adjb[i];
        if (t < Nn) s_idx[t] = nodes[b * Nn + t];
    }
    __syncthreads();

    if (t < En) {
        float s = 0.f;
        #pragma unroll 8
        for (int n = 0; n < Nn; n++) s += s_adj[n * En + t];
        s_dege[t] = fmaxf(s, 1.0f);
    }
    if (t >= 32 && t < 32 + Nn) {
        int n = t - 32;
        float s = 0.f;
        #pragma unroll
        for (int e = 0; e < En; e++) s += s_adj[n * En + e];
        s_degn[n] = fmaxf(s, 1.0f);
    }

    for (int n = wid; n < Nn; n += 8) {
        const float4 v = ((const float4*)(embedding + (size_t)s_idx[n] * Hn))[lane];
        float ss = v.x * v.x + v.y * v.y + v.z * v.z + v.w * v.w;
        #pragma unroll
        for (int o = 16; o > 0; o >>= 1) ss += __shfl_xor_sync(0xffffffffu, ss, o);
        const float inv = 1.0f / fmaxf(sqrtf(ss), EPS);
        ((float4*)(s_nh + n * SP))[lane] = make_float4(v.x * inv, v.y * inv, v.z * inv, v.w * inv);
    }
    __syncthreads();

    const int cw = wid * 16 + (lane & 3) * 4;
    const int rg = lane >> 2;

    for (int step = 0; step < 2; step++) {
        {
            const int d = t & 127;
            for (int e = t >> 7; e < En; e += 2) {
                float acc = 0.f;
                #pragma unroll 8
                for (int n = 0; n < Nn; n++) acc += s_adj[n * En + e] * s_nh[n * SP + d];
                s_tmp[e * SP + d] = acc / s_dege[e];
            }
        }
        __syncthreads();
        {
            float4 a0 = make_float4(0.f,0.f,0.f,0.f), a1 = make_float4(0.f,0.f,0.f,0.f);
            #pragma unroll 4
            for (int d = 0; d < Hn; d++) {
                const float4 wv = __ldg((const float4*)(w_edge + d * Hn + cw));
                const float t0 = s_tmp[rg * SP + d];
                const float t1 = s_tmp[(rg + 8) * SP + d];
                a0.x += t0 * wv.x; a0.y += t0 * wv.y; a0.z += t0 * wv.z; a0.w += t0 * wv.w;
                a1.x += t1 * wv.x; a1.y += t1 * wv.y; a1.z += t1 * wv.z; a1.w += t1 * wv.w;
            }
            *(float4*)(s_eh + rg * SP + cw)       = a0;
            *(float4*)(s_eh + (rg + 8) * SP + cw) = a1;
        }
        __syncthreads();
        {
            const int d = t & 127;
            for (int n = t >> 7; n < Nn; n += 2) {
                float acc = 0.f;
                #pragma unroll
                for (int e = 0; e < En; e++) acc += s_adj[n * En + e] * s_eh[e * SP + d];
                s_tmp[n * SP + d] = acc / s_degn[n];
            }
        }
        __syncthreads();
        {
            float acc[8][4];
            #pragma unroll
            for (int k = 0; k < 8; k++) { acc[k][0]=0; acc[k][1]=0; acc[k][2]=0; acc[k][3]=0; }
            #pragma unroll 4
            for (int d = 0; d < Hn; d++) {
                const float4 wv = __ldg((const float4*)(w_node + d * Hn + cw));
                #pragma unroll
                for (int k = 0; k < 8; k++) {
                    const float tv = s_tmp[(rg + 8 * k) * SP + d];
                    acc[k][0] += tv * wv.x; acc[k][1] += tv * wv.y;
                    acc[k][2] += tv * wv.z; acc[k][3] += tv * wv.w;
                }
            }
            #pragma unroll
            for (int k = 0; k < 8; k++)
                *(float4*)(s_nh + (rg + 8 * k) * SP + cw) =
                    make_float4(acc[k][0], acc[k][1], acc[k][2], acc[k][3]);
        }
        __syncthreads();
    }

    {
        float4* out4 = (float4*)(g_nodes_h + (size_t)b * Nn * Hn);
        for (int f = t; f < Nn * Hn / 4; f += 256) {
            const int row = f >> 5, c4 = f & 31;
            out4[f] = *(const float4*)(s_nh + row * SP + c4 * 4);
        }
    }
}

// =============================================================================
// prep_q2t: q2t[n][k] = q2_w[k][n]  (fp32 transpose)
// =============================================================================
__global__ void __launch_bounds__(256)
prep_q2t(const float* __restrict__ q2_w) {
    const int idx = blockIdx.x * 256 + threadIdx.x;   // 65536 total
    const int k = idx >> 8, n = idx & 255;
    g_q2t_f32[n * 256 + k] = q2_w[idx];
}

// =============================================================================
// seqbuild: seq[(b,l)] = l2norm(concat(nh[b,ai], nh[b,ac])) -> fp32
// =============================================================================
__global__ void __launch_bounds__(256)
seqbuild(const int* __restrict__ alias_item, const int* __restrict__ alias_cate) {
    const int rr = blockIdx.x * 8 + (threadIdx.x >> 5);
    const int lane = threadIdx.x & 31;
    if (rr >= Bn * Ln) return;
    const int b = rr / Ln;
    const int ai = alias_item[rr];
    const int ac = alias_cate[rr];
    const float4 vi = ((const float4*)(g_nodes_h + (size_t)(b * Nn + ai) * Hn))[lane];
    const float4 vc = ((const float4*)(g_nodes_h + (size_t)(b * Nn + ac) * Hn))[lane];
    float ss = vi.x*vi.x + vi.y*vi.y + vi.z*vi.z + vi.w*vi.w
             + vc.x*vc.x + vc.y*vc.y + vc.z*vc.z + vc.w*vc.w;
    #pragma unroll
    for (int o = 16; o > 0; o >>= 1) ss += __shfl_xor_sync(0xffffffffu, ss, o);
    const float inv = 1.0f / fmaxf(sqrtf(ss), EPS);
    ((float4*)(g_seq_f32 + (size_t)rr * Dn))[lane] =
        make_float4(vi.x*inv, vi.y*inv, vi.z*inv, vi.w*inv);
    ((float4*)(g_seq_f32 + (size_t)rr * Dn))[lane + 32] =
        make_float4(vc.x*inv, vc.y*inv, vc.z*inv, vc.w*inv);
}

// =============================================================================
// q2_sgemm: g_q2[m][n] = sum_k seq[m][k] * q2t[n][k]   (R1-PROVEN SGEMM core)
// A = q2t (256 rows), B = seq rows. Grid (2 n-tiles, 200 m-tiles).
// =============================================================================
__global__ void __launch_bounds__(256, 2)
q2_sgemm() {
    __shared__ float sA[16][132];   // [k][n]
    __shared__ float sB[16][132];   // [k][m]
    const int i0 = blockIdx.x * 128;   // n tile
    const int b0 = blockIdx.y * 128;   // m tile
    const int t = threadIdx.x;
    const int tx = t & 15, ty = t >> 4;
    const int lr = t >> 2;
    const int lk = (t & 3) << 2;

    float acc[8][8];
    #pragma unroll
    for (int ib = 0; ib < 8; ib++)
        #pragma unroll
        for (int ia = 0; ia < 8; ia++) acc[ib][ia] = 0.f;

    for (int k0 = 0; k0 < 256; k0 += 16) {
        if (k0) __syncthreads();
        #pragma unroll
        for (int h = 0; h < 2; h++) {
            const int irow = i0 + lr + h * 64;
            const float4 v = *(const float4*)(g_q2t_f32 + (size_t)irow * 256 + k0 + lk);
            sA[lk + 0][lr + h * 64] = v.x;
            sA[lk + 1][lr + h * 64] = v.y;
            sA[lk + 2][lr + h * 64] = v.z;
            sA[lk + 3][lr + h * 64] = v.w;
            const int brow = b0 + lr + h * 64;
            const float4 u = *(const float4*)(g_seq_f32 + (size_t)brow * 256 + k0 + lk);
            sB[lk + 0][lr + h * 64] = u.x;
            sB[lk + 1][lr + h * 64] = u.y;
            sB[lk + 2][lr + h * 64] = u.z;
            sB[lk + 3][lr + h * 64] = u.w;
        }
        __syncthreads();
        #pragma unroll
        for (int k = 0; k < 16; k++) {
            const float4 a0 = *(const float4*)&sA[k][tx * 4];
            const float4 a1 = *(const float4*)&sA[k][tx * 4 + 64];
            const float4 bb0 = *(const float4*)&sB[k][ty * 4];
            const float4 bb1 = *(const float4*)&sB[k][ty * 4 + 64];
            const float av[8] = {a0.x, a0.y, a0.z, a0.w, a1.x, a1.y, a1.z, a1.w};
            const float bv[8] = {bb0.x, bb0.y, bb0.z, bb0.w, bb1.x, bb1.y, bb1.z, bb1.w};
            #pragma unroll
            for (int ib = 0; ib < 8; ib++)
                #pragma unroll
                for (int ia = 0; ia < 8; ia++)
                    acc[ib][ia] += bv[ib] * av[ia];
        }
    }

    #pragma unroll
    for (int ib = 0; ib < 8; ib++) {
        const int brow = b0 + ty * 4 + ((ib < 4) ? ib : 60 + ib);
        float* crow = g_q2 + (size_t)brow * 256;
        const int ic0 = i0 + tx * 4;
        *(float4*)(crow + ic0) = make_float4(acc[ib][0], acc[ib][1], acc[ib][2], acc[ib][3]);
        const int ic1 = i0 + 64 + tx * 4;
        *(float4*)(crow + ic1) = make_float4(acc[ib][4], acc[ib][5], acc[ib][6], acc[ib][7]);
    }
}

// =============================================================================
// attn_lite: q1 + sigmoid + alpha + weighted sum + l2norm -> g_so hi/lo
// =============================================================================
__global__ void __launch_bounds__(256, 2)
attn_lite(const int* __restrict__ item_seq,
          const float* __restrict__ q1_w, const float* __restrict__ q1_b,
          const float* __restrict__ v_w) {
    __shared__ float s_ht[Dn];
    __shared__ float s_part[Ln * 8];
    __shared__ float s_alpha[Ln + 2];
    __shared__ float s_mask[Ln + 2];
    __shared__ float s_red[8];
    __shared__ float s_bcast;
    __shared__ int   s_last;

    const int b = blockIdx.x;
    const int t = threadIdx.x;
    const int lane = t & 31, wid = t >> 5;

    if (t < Ln) s_mask[t] = (item_seq[b * Ln + t] > 0) ? 1.0f : 0.0f;
    if (t == 0) {
        int cnt = 0;
        for (int l = 0; l < Ln; l++) cnt += (item_seq[b * Ln + l] > 0) ? 1 : 0;
        s_last = max(cnt - 1, 0);
    }
    __syncthreads();
    s_ht[t] = g_seq_f32[((size_t)b * Ln + s_last) * Dn + t];
    __syncthreads();

    float q1v = 0.f;
    #pragma unroll 4
    for (int d = 0; d < Dn; d++) q1v += s_ht[d] * q1_w[d * Dn + t];
    q1v += q1_b[t];

    const float vw = v_w[t];
    for (int l = 0; l < Ln; l++) {
        const float x = q1v + g_q2[((size_t)b * Ln + l) * Dn + t];
        float c = vw / (1.0f + expf(-x));
        #pragma unroll
        for (int o = 16; o > 0; o >>= 1) c += __shfl_xor_sync(0xffffffffu, c, o);
        if (lane == 0) s_part[l * 8 + wid] = c;
    }
    __syncthreads();
    if (t < Ln) {
        float a = 0.f;
        #pragma unroll
        for (int w = 0; w < 8; w++) a += s_part[t * 8 + w];
        s_alpha[t] = a * s_mask[t];
    }
    __syncthreads();

    float outacc = 0.f;
    #pragma unroll 5
    for (int l = 0; l < Ln; l++)
        outacc += s_alpha[l] * g_seq_f32[((size_t)b * Ln + l) * Dn + t];

    float ss = outacc * outacc;
    #pragma unroll
    for (int o = 16; o > 0; o >>= 1) ss += __shfl_xor_sync(0xffffffffu, ss, o);
    if (lane == 0) s_red[wid] = ss;
    __syncthreads();
    if (t == 0) {
        float a = 0.f;
        #pragma unroll
        for (int w = 0; w < 8; w++) a += s_red[w];
        s_bcast = a;
    }
    __syncthreads();
    const float inv = 1.0f / fmaxf(sqrtf(s_bcast), EPS);
    sthilo(g_so_hi, g_so_lo, (size_t)b * Dn + t, outacc * inv);
}

// =============================================================================
// itemnorm (R4 proven)
// =============================================================================
__global__ void __launch_bounds__(256)
itemnorm_kernel(const float* __restrict__ embedding, const int* __restrict__ item_cates) {
    const int i = blockIdx.x * 8 + (threadIdx.x >> 5);
    const int lane = threadIdx.x & 31;
    if (i >= ITEMN) return;
    const int c = item_cates[i];
    const float4 vi = ((const float4*)(embedding + (size_t)i * Hn))[lane];
    const float4 vc = ((const float4*)(embedding + (size_t)c * Hn))[lane];
    float ss = vi.x*vi.x + vi.y*vi.y + vi.z*vi.z + vi.w*vi.w
             + vc.x*vc.x + vc.y*vc.y + vc.z*vc.z + vc.w*vc.w;
    #pragma unroll
    for (int o = 16; o > 0; o >>= 1) ss += __shfl_xor_sync(0xffffffffu, ss, o);
    const float inv = 1.0f / fmaxf(sqrtf(ss), EPS);
    __nv_bfloat16* hi = g_item_hi + (size_t)i * Dn;
    __nv_bfloat16* lo = g_item_lo + (size_t)i * Dn;
    store4_hilo(hi, lo, lane * 4, make_float4(vi.x*inv, vi.y*inv, vi.z*inv, vi.w*inv));
    store4_hilo(hi, lo, 128 + lane * 4, make_float4(vc.x*inv, vc.y*inv, vc.z*inv, vc.w*inv));
}

// =============================================================================
// scores via HMMA split-bf16 (R4 proven)
// =============================================================================
#define ROWB 80
#define MATB (128 * ROWB)
#define BUFB (4 * MATB)
#define SC_SMEM (2 * BUFB)

__global__ void __launch_bounds__(256, 2)
scores_mma(float* __restrict__ C) {
    extern __shared__ char smc[];
    const uint32_t sb = smem_u32(smc);

    const int t = threadIdx.x;
    const int w = t >> 5, lane = t & 31;
    const int b0 = blockIdx.x * 128;
    const int i0 = blockIdx.y * 128;
    const int warp_m = w & 3;
    const int warp_n = w >> 2;

    const __nv_bfloat16* srcs[4] = {
        g_item_hi + (size_t)i0 * Dn, g_item_lo + (size_t)i0 * Dn,
        g_so_hi  + (size_t)b0 * Dn, g_so_lo  + (size_t)b0 * Dn
    };
    const int ld_row0 = t >> 2,  ld_seg0 = t & 3;
    const int ld_row1 = (256 + t) >> 2, ld_seg1 = t & 3;

    float acc[2][8][4];
    #pragma unroll
    for (int i = 0; i < 2; i++)
        #pragma unroll
        for (int j = 0; j < 8; j++)
            #pragma unroll
            for (int r = 0; r < 4; r++) acc[i][j][r] = 0.f;

    const uint32_t aA_lane = (uint32_t)((lane & 15) * ROWB + (lane >> 4) * 16);
    const uint32_t aB_lane = (uint32_t)(((lane & 7) + ((lane >> 4) & 1) * 8) * ROWB
                                        + ((lane >> 3) & 1) * 16);

    #pragma unroll
    for (int mat = 0; mat < 4; mat++) {
        cp16(sb + 0 * BUFB + mat * MATB + ld_row0 * ROWB + ld_seg0 * 16,
             srcs[mat] + ld_row0 * Dn + 0 + ld_seg0 * 8);
        cp16(sb + 0 * BUFB + mat * MATB + ld_row1 * ROWB + ld_seg1 * 16,
             srcs[mat] + ld_row1 * Dn + 0 + ld_seg1 * 8);
    }
    CP_COMMIT();

    for (int kc = 0; kc < 8; kc++) {
        const int buf = kc & 1;
        if (kc < 7) {
            const int k0 = (kc + 1) * 32;
            const int nbuf = (kc + 1) & 1;
            #pragma unroll
            for (int mat = 0; mat < 4; mat++) {
                cp16(sb + nbuf * BUFB + mat * MATB + ld_row0 * ROWB + ld_seg0 * 16,
                     srcs[mat] + ld_row0 * Dn + k0 + ld_seg0 * 8);
                cp16(sb + nbuf * BUFB + mat * MATB + ld_row1 * ROWB + ld_seg1 * 16,
                     srcs[mat] + ld_row1 * Dn + k0 + ld_seg1 * 8);
            }
            CP_COMMIT();
            CP_WAIT(1);
        } else {
            CP_WAIT(0);
        }
        __syncthreads();

        const uint32_t baseA = sb + buf * BUFB + (uint32_t)(warp_m * 32) * ROWB + aA_lane;
        const uint32_t baseB = sb + buf * BUFB + (uint32_t)(warp_n * 64) * ROWB + aB_lane;

        #pragma unroll
        for (int ks = 0; ks < 2; ks++) {
            const uint32_t koff = (uint32_t)ks * 32;
            uint32_t ahi[2][4], alo[2][4];
            #pragma unroll
            for (int i = 0; i < 2; i++) {
                ldsm4(ahi[i], baseA + 0 * MATB + (uint32_t)(i * 16) * ROWB + koff);
                ldsm4(alo[i], baseA + 1 * MATB + (uint32_t)(i * 16) * ROWB + koff);
            }
            #pragma unroll
            for (int jg = 0; jg < 2; jg++) {
                uint32_t bhi[2][4], blo[2][4];
                #pragma unroll
                for (int j4 = 0; j4 < 2; j4++) {
                    const uint32_t off = (uint32_t)((jg * 2 + j4) * 16) * ROWB + koff;
                    ldsm4(bhi[j4], baseB + 2 * MATB + off);
                    ldsm4(blo[j4], baseB + 3 * MATB + off);
                }
                #pragma unroll
                for (int i = 0; i < 2; i++)
                    #pragma unroll
                    for (int jj = 0; jj < 4; jj++) {
                        const int j = jg * 4 + jj;
                        const uint32_t* bh = &bhi[jj >> 1][(jj & 1) * 2];
                        const uint32_t* bl = &blo[jj >> 1][(jj & 1) * 2];
                        mma16816(acc[i][j], ahi[i], bh);
                        mma16816(acc[i][j], ahi[i], bl);
                        mma16816(acc[i][j], alo[i], bh);
                    }
            }
        }
        __syncthreads();
    }

    const int mrow = i0 + warp_m * 32 + (lane >> 2);
    const int ncol = b0 + warp_n * 64 + (lane & 3) * 2;
    #pragma unroll
    for (int i = 0; i < 2; i++) {
        #pragma unroll
        for (int j = 0; j < 8; j++) {
            const int n = ncol + j * 8;
            const int m = mrow + i * 16;
            if (m < ITEMN) {
                C[(size_t)n       * ITEMN + m]     = 16.f * acc[i][j][0];
                C[(size_t)(n + 1) * ITEMN + m]     = 16.f * acc[i][j][1];
            }
            if (m + 8 < ITEMN) {
                C[(size_t)n       * ITEMN + m + 8] = 16.f * acc[i][j][2];
                C[(size_t)(n + 1) * ITEMN + m + 8] = 16.f * acc[i][j][3];
            }
        }
    }
}

// =============================================================================
// launch
// =============================================================================
extern "C" void kernel_launch(void* const* d_in, const int* in_sizes, int n_in,
                              void* d_out, int out_size) {
    const int*   item_seq   = (const int*)  d_in[0];
    /* label d_in[1] unused */
    const int*   nodes      = (const int*)  d_in[2];
    const float* hn_adj     = (const float*)d_in[3];
    const int*   alias_item = (const int*)  d_in[4];
    const int*   alias_cate = (const int*)  d_in[5];
    const float* embedding  = (const float*)d_in[6];
    const int*   item_cates = (const int*)  d_in[7];
    const float* w_edge     = (const float*)d_in[8];
    const float* w_node     = (const float*)d_in[9];
    const float* q1_w       = (const float*)d_in[10];
    const float* q1_b       = (const float*)d_in[11];
    const float* q2_w       = (const float*)d_in[12];
    const float* v_w        = (const float*)d_in[13];
    float* out = (float*)d_out;

    const int hg_smem = (64 * SP + 64 * SP + 16 * SP + 1024 + 16 + 64 + 64) * 4;
    cudaFuncSetAttribute(hgnn_kernel, cudaFuncAttributeMaxDynamicSharedMemorySize, hg_smem);
    cudaFuncSetAttribute(scores_mma, cudaFuncAttributeMaxDynamicSharedMemorySize, SC_SMEM);

    prep_q2t<<<256, 256>>>(q2_w);
    itemnorm_kernel<<<(ITEMN + 7) / 8, 256>>>(embedding, item_cates);
    hgnn_kernel<<<Bn, 256, hg_smem>>>(nodes, hn_adj, embedding, w_edge, w_node);

    seqbuild<<<Bn * Ln / 8, 256>>>(alias_item, alias_cate);
    q2_sgemm<<<dim3(2, 200), 256>>>();
    attn_lite<<<Bn, 256>>>(item_seq, q1_w, q1_b, v_w);

    scores_mma<<<dim3(4, ITEMP / 128), 256, SC_SMEM>>>(out);
}